// round 2
// baseline (speedup 1.0000x reference)
#include <cuda_runtime.h>

#define TT 512
#define BB 512
#define KK 64
#define LOG2E 1.4426950408889634f
#define LN2   0.6931471805599453f

// scratch (device globals — no allocation)
__device__ float g_partial[BB];
__device__ int   g_is4;        // 0: mask is 1-byte elements, 1: 4-byte elements

__device__ __forceinline__ float ex2f_(float x) {
    float y; asm("ex2.approx.f32 %0, %1;" : "=f"(y) : "f"(x)); return y;
}
__device__ __forceinline__ float lg2f_(float x) {
    float y; asm("lg2.approx.f32 %0, %1;" : "=f"(y) : "f"(x)); return y;
}

// ---------------------------------------------------------------------------
// Mask-dtype detection. Scans only the first TT*BB bytes (safe under bool,
// int32 and float32 serializations). A genuine 1-byte one-hot mask has exactly
// BB nonzero bytes in that range; 4-byte serializations give far fewer.
// ---------------------------------------------------------------------------
__global__ void detect_mask_kernel(const unsigned char* __restrict__ m)
{
    __shared__ int cnt_s;
    if (threadIdx.x == 0) cnt_s = 0;
    __syncthreads();

    const uint4* w = (const uint4*)m;            // TT*BB/16 = 16384 uint4
    int local = 0;
    for (int i = threadIdx.x; i < (TT * BB) / 16; i += blockDim.x) {
        uint4 v = w[i];
        unsigned u;
        u = v.x; local += ((u & 0xFFu) != 0) + ((u & 0xFF00u) != 0) + ((u & 0xFF0000u) != 0) + ((u & 0xFF000000u) != 0);
        u = v.y; local += ((u & 0xFFu) != 0) + ((u & 0xFF00u) != 0) + ((u & 0xFF0000u) != 0) + ((u & 0xFF000000u) != 0);
        u = v.z; local += ((u & 0xFFu) != 0) + ((u & 0xFF00u) != 0) + ((u & 0xFF0000u) != 0) + ((u & 0xFF000000u) != 0);
        u = v.w; local += ((u & 0xFFu) != 0) + ((u & 0xFF00u) != 0) + ((u & 0xFF0000u) != 0) + ((u & 0xFF000000u) != 0);
    }
    atomicAdd(&cnt_s, local);
    __syncthreads();
    if (threadIdx.x == 0) g_is4 = (cnt_s == BB) ? 0 : 1;
}

// ---------------------------------------------------------------------------
// One CTA per batch element b; thread j = state index (K=64 threads, 2 warps).
// Base-2 log domain, lag-free shared-broadcast renormalizer:
//   p_i   = 2^(lfv_i)
//   s_j   = sum_i p_i * 2^(trans_ij*log2e)   (trans column j in registers)
//   lfv_j = log2(s_j) - r + emit_j*log2e ;  C2 += r   (r = lfv_0, broadcast)
// Exact invariant: true_log2_alpha_j = lfv_j + C2.
// Final per-b: LN2 * (C2 + log2(sum_j 2^lfv_j)).
// ---------------------------------------------------------------------------
__global__ __launch_bounds__(KK, 8)
void crf_forward_kernel(const float* __restrict__ emits,
                        const unsigned char* __restrict__ mask,
                        const float* __restrict__ trans,
                        const float* __restrict__ alpha0)
{
    __shared__ float p_s[2][KK];
    __shared__ float r_s[2];
    __shared__ int   stop_s;
    __shared__ float red_s[2];

    const int b = blockIdx.x;
    const int j = threadIdx.x;

    if (j == 0) stop_s = 0;
    __syncthreads();

    // one-hot mask position for this batch element (dtype-robust)
    if (g_is4) {
        const unsigned* m4 = (const unsigned*)mask;   // int32(1) or float32(1.0f): nonzero word
        for (int t = j; t < TT; t += KK)
            if (m4[t * BB + b]) atomicMax(&stop_s, t);
    } else {
        for (int t = j; t < TT; t += KK)
            if (mask[t * BB + b]) atomicMax(&stop_s, t);
    }

    // exp(trans) column j into registers (base-2 domain)
    float tr[KK];
    #pragma unroll
    for (int i = 0; i < KK; i++)
        tr[i] = ex2f_(trans[i * KK + j] * LOG2E);

    __syncthreads();
    const int stop = stop_s;  // uniform across block

    // fv0 = alpha0 + emits[0]
    float lfv = (alpha0[j] + emits[b * KK + j]) * LOG2E;
    float C2  = 0.0f;

    const float* eptr = emits + b * KK + j;
    float e_cur = (stop >= 1) ? eptr[1 * (BB * KK)] : 0.0f;

    int buf = 0;
    for (int t = 1; t <= stop; t++) {
        float e_next = (t < stop) ? eptr[(t + 1) * (BB * KK)] : 0.0f;  // prefetch

        p_s[buf][j] = ex2f_(lfv);
        if (j == 0) r_s[buf] = lfv;          // renormalizer for this step
        __syncthreads();                     // single barrier per step (double-buffered)

        const float4* p4 = (const float4*)p_s[buf];
        float s0 = 0.f, s1 = 0.f, s2 = 0.f, s3 = 0.f;
        #pragma unroll
        for (int i = 0; i < KK / 4; i++) {
            float4 v = p4[i];                // broadcast LDS.128 — conflict-free
            s0 = fmaf(v.x, tr[4 * i + 0], s0);
            s1 = fmaf(v.y, tr[4 * i + 1], s1);
            s2 = fmaf(v.z, tr[4 * i + 2], s2);
            s3 = fmaf(v.w, tr[4 * i + 3], s3);
        }
        float s = (s0 + s1) + (s2 + s3);

        float r = r_s[buf];
        C2 += r;
        lfv = fmaf(e_cur, LOG2E, lg2f_(s) - r);

        e_cur = e_next;
        buf ^= 1;
    }

    // per-b logsumexp over j (spread of lfv is bounded: no max pass needed)
    float v = ex2f_(lfv);
    #pragma unroll
    for (int o = 16; o > 0; o >>= 1)
        v += __shfl_xor_sync(0xffffffffu, v, o);
    if ((j & 31) == 0) red_s[j >> 5] = v;
    __syncthreads();
    if (j == 0) {
        float stot = red_s[0] + red_s[1];
        g_partial[b] = LN2 * (C2 + lg2f_(stot));
    }
}

// Deterministic 512 -> 1 sum
__global__ void crf_reduce_kernel(float* __restrict__ out)
{
    __shared__ float sm[16];
    const int tid = threadIdx.x;
    float v = g_partial[tid];
    #pragma unroll
    for (int o = 16; o > 0; o >>= 1)
        v += __shfl_xor_sync(0xffffffffu, v, o);
    if ((tid & 31) == 0) sm[tid >> 5] = v;
    __syncthreads();
    if (tid < 16) {
        float w = sm[tid];
        #pragma unroll
        for (int o = 8; o > 0; o >>= 1)
            w += __shfl_xor_sync(0x0000ffffu, w, o);
        if (tid == 0) out[0] = w;
    }
}

extern "C" void kernel_launch(void* const* d_in, const int* in_sizes, int n_in,
                              void* d_out, int out_size)
{
    // Identify inputs by element count (robust to metadata ordering):
    // emits 512*512*64=16777216, mask 512*512=262144, trans 64*64=4096, alpha0 64.
    const float*         emits  = 0;
    const unsigned char* mask   = 0;
    const float*         trans  = 0;
    const float*         alpha0 = 0;
    for (int i = 0; i < n_in; i++) {
        switch (in_sizes[i]) {
            case 16777216: emits  = (const float*)d_in[i];         break;
            case   262144: mask   = (const unsigned char*)d_in[i]; break;
            case     4096: trans  = (const float*)d_in[i];         break;
            case       64: alpha0 = (const float*)d_in[i];         break;
        }
    }

    detect_mask_kernel<<<1, 1024>>>(mask);
    crf_forward_kernel<<<BB, KK>>>(emits, mask, trans, alpha0);
    crf_reduce_kernel<<<1, BB>>>((float*)d_out);
}